// round 1
// baseline (speedup 1.0000x reference)
#include <cuda_runtime.h>
#include <math.h>

// Problem constants
#define BDIM 2
#define NSEQ 2048
#define LDIM 1024
#define DDIM 1024
#define HH   16
#define HDM  64
#define BNROWS (BDIM*NSEQ)   // 4096

static const long OUT1   = (long)BDIM * NSEQ * DDIM;        // 4,194,304
static const long AELEMS = (long)BDIM * HH * NSEQ * NSEQ;   // 134,217,728

// Scratch (device globals per harness rules: no cudaMalloc anywhere)
__device__ float g_Q[BNROWS * DDIM];
__device__ float g_K[BNROWS * DDIM];
__device__ float g_V[BNROWS * DDIM];   // becomes V*sigmoid(G)
__device__ float g_G[BNROWS * DDIM];   // sigmoid(G)
__device__ float g_M[BNROWS * DDIM];
__device__ float g_Y[BNROWS * DDIM];
__device__ float g_Afb[(size_t)BDIM * HH * NSEQ * NSEQ];  // fallback if A not part of output

// ---------------------------------------------------------------------------
// Generic batched SGEMM: C = alpha * A @ B' (+bias)(sigmoid?)(+resid)
//   A: [M,K] row-major, lda
//   B: NN -> [K,N] row-major, ldb ; NT (BT=true) -> [N,K] row-major, ldb (i.e. B transposed)
//   batch index z decomposed as (bb = z/Hdiv, hh = z%Hdiv); each operand gets
//   offset bb*s?b + hh*s?h.
// Requires M%BM==0, N%BN==0, K%BK==0, K%4==0, 16B-aligned base pointers.
// ---------------------------------------------------------------------------
template<int BM, int BN, int BK, int TM, int TN, bool BT>
__global__ __launch_bounds__((BM/TM)*(BN/TN))
void sgemm_kernel(int M, int N, int K,
                  const float* __restrict__ A, int lda, long sAb, long sAh,
                  const float* __restrict__ B, int ldb, long sBb, long sBh,
                  float* __restrict__ C, int ldc, long sCb, long sCh,
                  const float* __restrict__ bias,
                  const float* __restrict__ resid, int ldr, long sRb, long sRh,
                  float alpha, int act, int Hdiv)
{
    constexpr int THREADS = (BM/TM)*(BN/TN);
    constexpr int PAD = 4;

    int z  = blockIdx.z;
    int bb = z / Hdiv;
    int hh = z % Hdiv;
    A += bb * sAb + hh * sAh;
    B += bb * sBb + hh * sBh;
    C += bb * sCb + hh * sCh;
    if (resid) resid += bb * sRb + hh * sRh;

    __shared__ float As[BK][BM + PAD];
    __shared__ float Bs[BK][BN + PAD];

    const int tid     = threadIdx.x;
    const int tcols   = BN / TN;
    const int trow    = tid / tcols;
    const int tcol    = tid % tcols;
    const int rowBase = blockIdx.y * BM;
    const int colBase = blockIdx.x * BN;

    float acc[TM][TN];
#pragma unroll
    for (int i = 0; i < TM; i++)
#pragma unroll
        for (int j = 0; j < TN; j++) acc[i][j] = 0.f;

    for (int k0 = 0; k0 < K; k0 += BK) {
        // Load A tile (BM x BK), float4 along K, store transposed As[k][m]
        constexpr int A4 = BM * BK / 4;
        for (int idx = tid; idx < A4; idx += THREADS) {
            int r  = idx / (BK / 4);
            int c4 = idx % (BK / 4);
            float4 v = *(const float4*)(A + (long)(rowBase + r) * lda + k0 + c4 * 4);
            As[c4*4+0][r] = v.x; As[c4*4+1][r] = v.y;
            As[c4*4+2][r] = v.z; As[c4*4+3][r] = v.w;
        }
        // Load B tile -> Bs[k][n]
        constexpr int B4 = BK * BN / 4;
        if (!BT) {
            for (int idx = tid; idx < B4; idx += THREADS) {
                int r  = idx / (BN / 4);
                int c4 = idx % (BN / 4);
                float4 v = *(const float4*)(B + (long)(k0 + r) * ldb + colBase + c4 * 4);
                *(float4*)&Bs[r][c4 * 4] = v;
            }
        } else {
            for (int idx = tid; idx < B4; idx += THREADS) {
                int n  = idx / (BK / 4);
                int c4 = idx % (BK / 4);
                float4 v = *(const float4*)(B + (long)(colBase + n) * ldb + k0 + c4 * 4);
                Bs[c4*4+0][n] = v.x; Bs[c4*4+1][n] = v.y;
                Bs[c4*4+2][n] = v.z; Bs[c4*4+3][n] = v.w;
            }
        }
        __syncthreads();

#pragma unroll
        for (int kk = 0; kk < BK; kk++) {
            float ra[TM], rb[TN];
#pragma unroll
            for (int i = 0; i < TM; i++) ra[i] = As[kk][trow * TM + i];
#pragma unroll
            for (int j = 0; j < TN; j++) rb[j] = Bs[kk][tcol * TN + j];
#pragma unroll
            for (int i = 0; i < TM; i++)
#pragma unroll
                for (int j = 0; j < TN; j++)
                    acc[i][j] = fmaf(ra[i], rb[j], acc[i][j]);
        }
        __syncthreads();
    }

    // Epilogue
#pragma unroll
    for (int i = 0; i < TM; i++) {
        int r = rowBase + trow * TM + i;
#pragma unroll
        for (int j = 0; j < TN; j++) {
            int c = colBase + tcol * TN + j;
            float v = acc[i][j] * alpha;
            if (bias)  v += bias[c];
            if (act == 1) v = 1.f / (1.f + expf(-v));
            if (resid) v += resid[(long)r * ldr + c];
            C[(long)r * ldc + c] = v;
        }
    }
}

// V *= sigmoid(G) (G already post-sigmoid); float4 elementwise
__global__ void vg_kernel(float* __restrict__ V, const float* __restrict__ G)
{
    long i = (long)blockIdx.x * blockDim.x + threadIdx.x;
    float4 v = ((const float4*)V)[i];
    float4 g = ((const float4*)G)[i];
    v.x *= g.x; v.y *= g.y; v.z *= g.z; v.w *= g.w;
    ((float4*)V)[i] = v;
}

// In-place softmax over rows of length NSEQ (2048). 256 threads, 8 elems each.
__global__ void softmax_kernel(float* __restrict__ A)
{
    __shared__ float red[256];
    long row = blockIdx.x;
    float* p = A + row * (long)NSEQ;
    int tid = threadIdx.x;

    float4 a = ((const float4*)p)[tid];
    float4 b = ((const float4*)p)[tid + 256];

    float m = fmaxf(fmaxf(fmaxf(a.x, a.y), fmaxf(a.z, a.w)),
                    fmaxf(fmaxf(b.x, b.y), fmaxf(b.z, b.w)));
    red[tid] = m; __syncthreads();
    for (int o = 128; o > 0; o >>= 1) {
        if (tid < o) red[tid] = fmaxf(red[tid], red[tid + o]);
        __syncthreads();
    }
    m = red[0]; __syncthreads();

    a.x = expf(a.x - m); a.y = expf(a.y - m); a.z = expf(a.z - m); a.w = expf(a.w - m);
    b.x = expf(b.x - m); b.y = expf(b.y - m); b.z = expf(b.z - m); b.w = expf(b.w - m);
    float s = a.x + a.y + a.z + a.w + b.x + b.y + b.z + b.w;
    red[tid] = s; __syncthreads();
    for (int o = 128; o > 0; o >>= 1) {
        if (tid < o) red[tid] += red[tid + o];
        __syncthreads();
    }
    float inv = 1.f / red[0];

    a.x *= inv; a.y *= inv; a.z *= inv; a.w *= inv;
    b.x *= inv; b.y *= inv; b.z *= inv; b.w *= inv;
    ((float4*)p)[tid]       = a;
    ((float4*)p)[tid + 256] = b;
}

// LayerNorm over last dim (1024). One block (256 thr * float4) per row.
__global__ void ln_kernel(const float* __restrict__ Y,
                          const float* __restrict__ gamma,
                          const float* __restrict__ beta,
                          float* __restrict__ out)
{
    __shared__ float red[256];
    int row = blockIdx.x, tid = threadIdx.x;
    const float4* y4 = (const float4*)(Y + (long)row * DDIM);
    float4 v = y4[tid];

    red[tid] = v.x + v.y + v.z + v.w; __syncthreads();
    for (int o = 128; o > 0; o >>= 1) {
        if (tid < o) red[tid] += red[tid + o];
        __syncthreads();
    }
    float mean = red[0] * (1.f / DDIM);
    __syncthreads();

    float d0 = v.x - mean, d1 = v.y - mean, d2 = v.z - mean, d3 = v.w - mean;
    red[tid] = d0*d0 + d1*d1 + d2*d2 + d3*d3; __syncthreads();
    for (int o = 128; o > 0; o >>= 1) {
        if (tid < o) red[tid] += red[tid + o];
        __syncthreads();
    }
    float var = red[0] * (1.f / DDIM);
    float inv = rsqrtf(var + 1e-5f);

    float4 g  = ((const float4*)gamma)[tid];
    float4 bt = ((const float4*)beta)[tid];
    float4 o4;
    o4.x = g.x * (d0 * inv) + bt.x;
    o4.y = g.y * (d1 * inv) + bt.y;
    o4.z = g.z * (d2 * inv) + bt.z;
    o4.w = g.w * (d3 * inv) + bt.w;
    ((float4*)(out + (long)row * DDIM))[tid] = o4;
}

extern "C" void kernel_launch(void* const* d_in, const int* in_sizes, int n_in,
                              void* d_out, int out_size)
{
    const float* x     = (const float*)d_in[0];
    const float* Wq    = (const float*)d_in[1];
    const float* bq    = (const float*)d_in[2];
    const float* Wk    = (const float*)d_in[3];
    const float* bk    = (const float*)d_in[4];
    const float* Wv    = (const float*)d_in[5];
    const float* bv    = (const float*)d_in[6];
    const float* Wg    = (const float*)d_in[7];
    const float* bg    = (const float*)d_in[8];
    const float* Wp    = (const float*)d_in[9];
    const float* bp    = (const float*)d_in[10];
    const float* gamma = (const float*)d_in[11];
    const float* beta  = (const float*)d_in[12];
    float* out = (float*)d_out;

    float *Q, *K, *V, *G, *Mb, *Y, *Afb;
    cudaGetSymbolAddress((void**)&Q,   g_Q);
    cudaGetSymbolAddress((void**)&K,   g_K);
    cudaGetSymbolAddress((void**)&V,   g_V);
    cudaGetSymbolAddress((void**)&G,   g_G);
    cudaGetSymbolAddress((void**)&Mb,  g_M);
    cudaGetSymbolAddress((void**)&Y,   g_Y);
    cudaGetSymbolAddress((void**)&Afb, g_Afb);

    float* A = ((long)out_size >= OUT1 + AELEMS) ? (out + OUT1) : Afb;

    dim3 blk(256);

    // 1) Projections: (4096x1024) @ (1024x1024) + bias  [G gets sigmoid]
    {
        dim3 grid(DDIM / 128, BNROWS / 128, 1);
        sgemm_kernel<128,128,8,8,8,false><<<grid, blk>>>(
            BNROWS, DDIM, LDIM, x, LDIM, 0, 0, Wq, DDIM, 0, 0, Q, DDIM, 0, 0,
            bq, nullptr, 0, 0, 0, 1.f, 0, 1);
        sgemm_kernel<128,128,8,8,8,false><<<grid, blk>>>(
            BNROWS, DDIM, LDIM, x, LDIM, 0, 0, Wk, DDIM, 0, 0, K, DDIM, 0, 0,
            bk, nullptr, 0, 0, 0, 1.f, 0, 1);
        sgemm_kernel<128,128,8,8,8,false><<<grid, blk>>>(
            BNROWS, DDIM, LDIM, x, LDIM, 0, 0, Wv, DDIM, 0, 0, V, DDIM, 0, 0,
            bv, nullptr, 0, 0, 0, 1.f, 0, 1);
        sgemm_kernel<128,128,8,8,8,false><<<grid, blk>>>(
            BNROWS, DDIM, LDIM, x, LDIM, 0, 0, Wg, DDIM, 0, 0, G, DDIM, 0, 0,
            bg, nullptr, 0, 0, 0, 1.f, 1, 1);
    }

    // 2) V = V * sigmoid(G)
    vg_kernel<<<(BNROWS * DDIM) / (256 * 4), blk>>>(V, G);

    // 3) Scores: per (b,h): S = (1/8) * Qh @ Kh^T  -> raw scores into A region
    {
        dim3 grid(NSEQ / 128, NSEQ / 128, BDIM * HH);
        sgemm_kernel<128,128,8,8,8,true><<<grid, blk>>>(
            NSEQ, NSEQ, HDM,
            Q, DDIM, (long)NSEQ * DDIM, HDM,
            K, DDIM, (long)NSEQ * DDIM, HDM,
            A, NSEQ, (long)HH * NSEQ * NSEQ, (long)NSEQ * NSEQ,
            nullptr, nullptr, 0, 0, 0, 0.125f, 0, HH);
    }

    // 4) Row softmax in place on A
    softmax_kernel<<<BDIM * HH * NSEQ, blk>>>(A);

    // 5) M = A @ (V*G) per (b,h)
    {
        dim3 grid(HDM / 64, NSEQ / 128, BDIM * HH);
        sgemm_kernel<128,64,8,8,4,false><<<grid, blk>>>(
            NSEQ, HDM, NSEQ,
            A, NSEQ, (long)HH * NSEQ * NSEQ, (long)NSEQ * NSEQ,
            V, DDIM, (long)NSEQ * DDIM, HDM,
            Mb, DDIM, (long)NSEQ * DDIM, HDM,
            nullptr, nullptr, 0, 0, 0, 1.f, 0, HH);
    }

    // 6) Output projection + residual: Y = x + M @ Wp + bp
    {
        dim3 grid(DDIM / 128, BNROWS / 128, 1);
        sgemm_kernel<128,128,8,8,8,false><<<grid, blk>>>(
            BNROWS, DDIM, DDIM, Mb, DDIM, 0, 0, Wp, DDIM, 0, 0, Y, DDIM, 0, 0,
            bp, x, DDIM, 0, 0, 1.f, 0, 1);
    }

    // 7) LayerNorm -> out
    ln_kernel<<<BNROWS, blk>>>(Y, gamma, beta, out);
}

// round 3
// speedup vs baseline: 2.2518x; 2.2518x over previous
#include <cuda_runtime.h>
#include <cuda_bf16.h>
#include <math.h>

// Problem constants
#define BDIM 2
#define NSEQ 2048
#define LDIM 1024
#define DDIM 1024
#define HH   16
#define HDM  64
#define BNROWS (BDIM*NSEQ)   // 4096

static const long OUT1   = (long)BDIM * NSEQ * DDIM;        // 4,194,304
static const long AELEMS = (long)BDIM * HH * NSEQ * NSEQ;   // 134,217,728

// Scratch (device globals: no cudaMalloc anywhere)
__device__ float g_Q[BNROWS * DDIM];
__device__ float g_K[BNROWS * DDIM];
__device__ float g_V[BNROWS * DDIM];   // becomes V*sigmoid(G)
__device__ float g_G[BNROWS * DDIM];
__device__ float g_M[BNROWS * DDIM];
__device__ float g_Y[BNROWS * DDIM];
__device__ float g_Afb[(size_t)BDIM * HH * NSEQ * NSEQ];  // fallback if A not in output

__device__ __forceinline__ unsigned smem_u32(const void* p) {
    return (unsigned)__cvta_generic_to_shared(p);
}

__device__ __forceinline__ void ldm_x4(unsigned* d, unsigned addr) {
    asm volatile("ldmatrix.sync.aligned.m8n8.x4.shared.b16 {%0,%1,%2,%3}, [%4];"
                 : "=r"(d[0]), "=r"(d[1]), "=r"(d[2]), "=r"(d[3]) : "r"(addr));
}
__device__ __forceinline__ void ldm_x4t(unsigned* d, unsigned addr) {
    asm volatile("ldmatrix.sync.aligned.m8n8.x4.trans.shared.b16 {%0,%1,%2,%3}, [%4];"
                 : "=r"(d[0]), "=r"(d[1]), "=r"(d[2]), "=r"(d[3]) : "r"(addr));
}
__device__ __forceinline__ void mma_bf16(float* c, const unsigned* a, const unsigned* b) {
    asm volatile(
        "mma.sync.aligned.m16n8k16.row.col.f32.bf16.bf16.f32 "
        "{%0,%1,%2,%3},{%4,%5,%6,%7},{%8,%9},{%0,%1,%2,%3};"
        : "+f"(c[0]), "+f"(c[1]), "+f"(c[2]), "+f"(c[3])
        : "r"(a[0]), "r"(a[1]), "r"(a[2]), "r"(a[3]), "r"(b[0]), "r"(b[1]));
}

__device__ __forceinline__ void split_bf16(float v, __nv_bfloat16& h, __nv_bfloat16& l) {
    h = __float2bfloat16_rn(v);
    l = __float2bfloat16_rn(v - __bfloat162float(h));
}

// ---------------------------------------------------------------------------
// bf16x3 error-compensated batched GEMM (tensor cores, fp32 in/out):
//   C = alpha * A @ B' (+bias)(sigmoid?)(+resid)
//   A: [M,K] row-major, lda. B: NN -> [K,N] row-major; BT -> [N,K] row-major.
// ---------------------------------------------------------------------------
template<int BM, int BN, int BK, int WM, int WN, bool BT>
__global__ __launch_bounds__((BM/WM)*(BN/WN)*32)
void mma_gemm(int M, int N, int K,
              const float* __restrict__ A, int lda, long sAb, long sAh,
              const float* __restrict__ B, int ldb, long sBb, long sBh,
              float* __restrict__ C, int ldc, long sCb, long sCh,
              const float* __restrict__ bias,
              const float* __restrict__ resid, int ldr,
              float alpha, int act, int Hdiv)
{
    constexpr int WARPS   = (BM/WM)*(BN/WN);
    constexpr int THREADS = WARPS * 32;
    constexpr int APAD = 8, BPAD = 8;
    constexpr int MI = WM/16, NJ = WN/8;

    __shared__ __align__(16) __nv_bfloat16 Ah[BM][BK+APAD];
    __shared__ __align__(16) __nv_bfloat16 Al[BM][BK+APAD];
    __shared__ __align__(16) __nv_bfloat16 Bh[BK][BN+BPAD];
    __shared__ __align__(16) __nv_bfloat16 Bl[BK][BN+BPAD];

    int z  = blockIdx.z;
    int bb = z / Hdiv;
    int hh = z - bb * Hdiv;
    A += bb * sAb + hh * sAh;
    B += bb * sBb + hh * sBh;
    C += bb * sCb + hh * sCh;

    const int tid  = threadIdx.x;
    const int lane = tid & 31;
    const int warp = tid >> 5;
    const int wm = warp % (BM/WM);
    const int wn = warp / (BM/WM);
    const int m0 = wm * WM, n0 = wn * WN;
    const int rowBase = blockIdx.y * BM;
    const int colBase = blockIdx.x * BN;

    const int lrow  = lane & 15;          // row within 16-row tile
    const int lkoff = (lane >> 4) << 3;   // 0 or 8

    float acc[MI][NJ][4];
#pragma unroll
    for (int i = 0; i < MI; i++)
#pragma unroll
        for (int j = 0; j < NJ; j++)
#pragma unroll
            for (int q = 0; q < 4; q++) acc[i][j][q] = 0.f;

    for (int k0 = 0; k0 < K; k0 += BK) {
        // ---- stage A tile (BM x BK) with hi/lo split ----
        constexpr int A4 = BM * (BK/4);
#pragma unroll
        for (int t = 0; t < A4; t += THREADS) {
            int idx = t + tid;
            int r = idx / (BK/4);
            int c = (idx % (BK/4)) * 4;
            float4 v = *(const float4*)(A + (long)(rowBase + r) * lda + k0 + c);
            __nv_bfloat16 h0, h1, h2, h3, l0, l1, l2, l3;
            split_bf16(v.x, h0, l0); split_bf16(v.y, h1, l1);
            split_bf16(v.z, h2, l2); split_bf16(v.w, h3, l3);
            __nv_bfloat162 p;
            p.x = h0; p.y = h1; *(__nv_bfloat162*)&Ah[r][c]   = p;
            p.x = h2; p.y = h3; *(__nv_bfloat162*)&Ah[r][c+2] = p;
            p.x = l0; p.y = l1; *(__nv_bfloat162*)&Al[r][c]   = p;
            p.x = l2; p.y = l3; *(__nv_bfloat162*)&Al[r][c+2] = p;
        }
        // ---- stage B tile -> Bs[k][n] with hi/lo split ----
        if (!BT) {
            constexpr int B4 = BK * (BN/4);
#pragma unroll
            for (int t = 0; t < B4; t += THREADS) {
                int idx = t + tid;
                int r = idx / (BN/4);
                int c = (idx % (BN/4)) * 4;
                float4 v = *(const float4*)(B + (long)(k0 + r) * ldb + colBase + c);
                __nv_bfloat16 h0, h1, h2, h3, l0, l1, l2, l3;
                split_bf16(v.x, h0, l0); split_bf16(v.y, h1, l1);
                split_bf16(v.z, h2, l2); split_bf16(v.w, h3, l3);
                __nv_bfloat162 p;
                p.x = h0; p.y = h1; *(__nv_bfloat162*)&Bh[r][c]   = p;
                p.x = h2; p.y = h3; *(__nv_bfloat162*)&Bh[r][c+2] = p;
                p.x = l0; p.y = l1; *(__nv_bfloat162*)&Bl[r][c]   = p;
                p.x = l2; p.y = l3; *(__nv_bfloat162*)&Bl[r][c+2] = p;
            }
        } else {
            constexpr int B4 = BN * (BK/4);
#pragma unroll
            for (int t = 0; t < B4; t += THREADS) {
                int idx = t + tid;
                int n = idx / (BK/4);
                int c = (idx % (BK/4)) * 4;
                float4 v = *(const float4*)(B + (long)(colBase + n) * ldb + k0 + c);
                float vv[4] = {v.x, v.y, v.z, v.w};
#pragma unroll
                for (int j = 0; j < 4; j++) {
                    __nv_bfloat16 h, l;
                    split_bf16(vv[j], h, l);
                    Bh[c + j][n] = h;
                    Bl[c + j][n] = l;
                }
            }
        }
        __syncthreads();

        // ---- compute: BK/16 k-steps, 3 mma passes (hh, hl, lh) ----
#pragma unroll
        for (int kk = 0; kk < BK; kk += 16) {
            unsigned afh[MI][4], afl[MI][4];
            unsigned bfh[NJ][2], bfl[NJ][2];
#pragma unroll
            for (int mi = 0; mi < MI; mi++) {
                ldm_x4(afh[mi], smem_u32(&Ah[m0 + mi*16 + lrow][kk + lkoff]));
                ldm_x4(afl[mi], smem_u32(&Al[m0 + mi*16 + lrow][kk + lkoff]));
            }
#pragma unroll
            for (int nj = 0; nj < NJ; nj += 2) {
                ldm_x4t(&bfh[nj][0], smem_u32(&Bh[kk + lrow][n0 + (nj + (lane >> 4)) * 8]));
                ldm_x4t(&bfl[nj][0], smem_u32(&Bl[kk + lrow][n0 + (nj + (lane >> 4)) * 8]));
            }
#pragma unroll
            for (int mi = 0; mi < MI; mi++)
#pragma unroll
                for (int nj = 0; nj < NJ; nj++) {
                    mma_bf16(acc[mi][nj], afh[mi], bfh[nj]);
                    mma_bf16(acc[mi][nj], afh[mi], bfl[nj]);
                    mma_bf16(acc[mi][nj], afl[mi], bfh[nj]);
                }
        }
        __syncthreads();
    }

    // ---- epilogue ----
#pragma unroll
    for (int mi = 0; mi < MI; mi++) {
#pragma unroll
        for (int nj = 0; nj < NJ; nj++) {
            int c = colBase + n0 + nj*8 + 2*(lane & 3);
            float b0 = 0.f, b1 = 0.f;
            if (bias) { b0 = bias[c]; b1 = bias[c+1]; }
#pragma unroll
            for (int half = 0; half < 2; half++) {
                int r = rowBase + m0 + mi*16 + (lane >> 2) + half*8;
                float v0 = acc[mi][nj][half*2+0] * alpha + b0;
                float v1 = acc[mi][nj][half*2+1] * alpha + b1;
                if (act == 1) {
                    v0 = 1.f / (1.f + __expf(-v0));
                    v1 = 1.f / (1.f + __expf(-v1));
                }
                if (resid) {
                    v0 += resid[(long)r * ldr + c];
                    v1 += resid[(long)r * ldr + c + 1];
                }
                float2 o; o.x = v0; o.y = v1;
                *(float2*)&C[(long)r * ldc + c] = o;
            }
        }
    }
}

// V *= sigmoid(G) (G already post-sigmoid)
__global__ void vg_kernel(float* __restrict__ V, const float* __restrict__ G)
{
    long i = (long)blockIdx.x * blockDim.x + threadIdx.x;
    float4 v = ((const float4*)V)[i];
    float4 g = ((const float4*)G)[i];
    v.x *= g.x; v.y *= g.y; v.z *= g.z; v.w *= g.w;
    ((float4*)V)[i] = v;
}

// In-place softmax over rows of length NSEQ (2048). 256 threads, 8 elems each.
__global__ void softmax_kernel(float* __restrict__ A)
{
    __shared__ float red[256];
    long row = blockIdx.x;
    float* p = A + row * (long)NSEQ;
    int tid = threadIdx.x;

    float4 a = ((const float4*)p)[tid];
    float4 b = ((const float4*)p)[tid + 256];

    float m = fmaxf(fmaxf(fmaxf(a.x, a.y), fmaxf(a.z, a.w)),
                    fmaxf(fmaxf(b.x, b.y), fmaxf(b.z, b.w)));
    red[tid] = m; __syncthreads();
    for (int o = 128; o > 0; o >>= 1) {
        if (tid < o) red[tid] = fmaxf(red[tid], red[tid + o]);
        __syncthreads();
    }
    m = red[0]; __syncthreads();

    a.x = expf(a.x - m); a.y = expf(a.y - m); a.z = expf(a.z - m); a.w = expf(a.w - m);
    b.x = expf(b.x - m); b.y = expf(b.y - m); b.z = expf(b.z - m); b.w = expf(b.w - m);
    float s = a.x + a.y + a.z + a.w + b.x + b.y + b.z + b.w;
    red[tid] = s; __syncthreads();
    for (int o = 128; o > 0; o >>= 1) {
        if (tid < o) red[tid] += red[tid + o];
        __syncthreads();
    }
    float inv = 1.f / red[0];

    a.x *= inv; a.y *= inv; a.z *= inv; a.w *= inv;
    b.x *= inv; b.y *= inv; b.z *= inv; b.w *= inv;
    ((float4*)p)[tid]       = a;
    ((float4*)p)[tid + 256] = b;
}

// LayerNorm over last dim (1024). One block (256 thr * float4) per row.
__global__ void ln_kernel(const float* __restrict__ Y,
                          const float* __restrict__ gamma,
                          const float* __restrict__ beta,
                          float* __restrict__ out)
{
    __shared__ float red[256];
    int row = blockIdx.x, tid = threadIdx.x;
    const float4* y4 = (const float4*)(Y + (long)row * DDIM);
    float4 v = y4[tid];

    red[tid] = v.x + v.y + v.z + v.w; __syncthreads();
    for (int o = 128; o > 0; o >>= 1) {
        if (tid < o) red[tid] += red[tid + o];
        __syncthreads();
    }
    float mean = red[0] * (1.f / DDIM);
    __syncthreads();

    float d0 = v.x - mean, d1 = v.y - mean, d2 = v.z - mean, d3 = v.w - mean;
    red[tid] = d0*d0 + d1*d1 + d2*d2 + d3*d3; __syncthreads();
    for (int o = 128; o > 0; o >>= 1) {
        if (tid < o) red[tid] += red[tid + o];
        __syncthreads();
    }
    float var = red[0] * (1.f / DDIM);
    float inv = rsqrtf(var + 1e-5f);

    float4 g  = ((const float4*)gamma)[tid];
    float4 bt = ((const float4*)beta)[tid];
    float4 o4;
    o4.x = g.x * (d0 * inv) + bt.x;
    o4.y = g.y * (d1 * inv) + bt.y;
    o4.z = g.z * (d2 * inv) + bt.z;
    o4.w = g.w * (d3 * inv) + bt.w;
    ((float4*)(out + (long)row * DDIM))[tid] = o4;
}

extern "C" void kernel_launch(void* const* d_in, const int* in_sizes, int n_in,
                              void* d_out, int out_size)
{
    const float* x     = (const float*)d_in[0];
    const float* Wq    = (const float*)d_in[1];
    const float* bq    = (const float*)d_in[2];
    const float* Wk    = (const float*)d_in[3];
    const float* bk    = (const float*)d_in[4];
    const float* Wv    = (const float*)d_in[5];
    const float* bv    = (const float*)d_in[6];
    const float* Wg    = (const float*)d_in[7];
    const float* bg    = (const float*)d_in[8];
    const float* Wp    = (const float*)d_in[9];
    const float* bp    = (const float*)d_in[10];
    const float* gamma = (const float*)d_in[11];
    const float* beta  = (const float*)d_in[12];
    float* outp = (float*)d_out;

    float *Q, *K, *V, *G, *Mb, *Y, *Afb;
    cudaGetSymbolAddress((void**)&Q,   g_Q);
    cudaGetSymbolAddress((void**)&K,   g_K);
    cudaGetSymbolAddress((void**)&V,   g_V);
    cudaGetSymbolAddress((void**)&G,   g_G);
    cudaGetSymbolAddress((void**)&Mb,  g_M);
    cudaGetSymbolAddress((void**)&Y,   g_Y);
    cudaGetSymbolAddress((void**)&Afb, g_Afb);

    float* A = ((long)out_size >= OUT1 + AELEMS) ? (outp + OUT1) : Afb;

    // 1) Projections: (4096x1024)@(1024x1024)+bias  [G -> sigmoid]
    {
        dim3 grid(DDIM/128, BNROWS/128, 1);
        mma_gemm<128,128,32,64,32,false><<<grid, 256>>>(
            BNROWS, DDIM, LDIM, x, LDIM, 0, 0, Wq, DDIM, 0, 0, Q, DDIM, 0, 0,
            bq, nullptr, 0, 1.f, 0, 1);
        mma_gemm<128,128,32,64,32,false><<<grid, 256>>>(
            BNROWS, DDIM, LDIM, x, LDIM, 0, 0, Wk, DDIM, 0, 0, K, DDIM, 0, 0,
            bk, nullptr, 0, 1.f, 0, 1);
        mma_gemm<128,128,32,64,32,false><<<grid, 256>>>(
            BNROWS, DDIM, LDIM, x, LDIM, 0, 0, Wv, DDIM, 0, 0, V, DDIM, 0, 0,
            bv, nullptr, 0, 1.f, 0, 1);
        mma_gemm<128,128,32,64,32,false><<<grid, 256>>>(
            BNROWS, DDIM, LDIM, x, LDIM, 0, 0, Wg, DDIM, 0, 0, G, DDIM, 0, 0,
            bg, nullptr, 0, 1.f, 1, 1);
    }

    // 2) V = V * sigmoid(G)
    vg_kernel<<<(BNROWS * DDIM) / (256 * 4), 256>>>(V, G);

    // 3) Scores: per (b,h): S = (1/8) * Qh @ Kh^T  -> raw scores into A region
    {
        dim3 grid(NSEQ/128, NSEQ/128, BDIM*HH);
        mma_gemm<128,128,32,64,32,true><<<grid, 256>>>(
            NSEQ, NSEQ, HDM,
            Q, DDIM, (long)NSEQ*DDIM, HDM,
            K, DDIM, (long)NSEQ*DDIM, HDM,
            A, NSEQ, (long)HH*NSEQ*NSEQ, (long)NSEQ*NSEQ,
            nullptr, nullptr, 0, 0.125f, 0, HH);
    }

    // 4) Row softmax in place on A
    softmax_kernel<<<BDIM*HH*NSEQ, 256>>>(A);

    // 5) M = A @ (V*G) per (b,h)
    {
        dim3 grid(1, NSEQ/128, BDIM*HH);
        mma_gemm<128,64,32,64,32,false><<<grid, 128>>>(
            NSEQ, HDM, NSEQ,
            A, NSEQ, (long)HH*NSEQ*NSEQ, (long)NSEQ*NSEQ,
            V, DDIM, (long)NSEQ*DDIM, HDM,
            Mb, DDIM, (long)NSEQ*DDIM, HDM,
            nullptr, nullptr, 0, 1.f, 0, HH);
    }

    // 6) Output projection + residual: Y = x + M @ Wp + bp
    {
        dim3 grid(DDIM/128, BNROWS/128, 1);
        mma_gemm<128,128,32,64,32,false><<<grid, 256>>>(
            BNROWS, DDIM, DDIM, Mb, DDIM, 0, 0, Wp, DDIM, 0, 0, Y, DDIM, 0, 0,
            bp, x, DDIM, 1.f, 0, 0);
    }

    // 7) LayerNorm -> out
    ln_kernel<<<BNROWS, 256>>>(Y, gamma, beta, outp);
}

// round 4
// speedup vs baseline: 2.7454x; 1.2192x over previous
#include <cuda_runtime.h>
#include <cuda_bf16.h>
#include <math.h>

#define BDIM 2
#define NSEQ 2048
#define LDIM 1024
#define DDIM 1024
#define HH   16
#define HDM  64
#define BNROWS (BDIM*NSEQ)   // 4096

static const long OUT1   = (long)BDIM * NSEQ * DDIM;        // 4,194,304
static const long AELEMS = (long)BDIM * HH * NSEQ * NSEQ;   // 134,217,728

typedef __nv_bfloat16 bf16;
typedef __nv_bfloat162 bf162;

// ---------------- device scratch (no cudaMalloc anywhere) ----------------
__device__ __align__(256) bf16 g_xh[BNROWS*LDIM], g_xl[BNROWS*LDIM];
__device__ __align__(256) bf16 g_wh[5][LDIM*DDIM], g_wl[5][LDIM*DDIM];
__device__ __align__(256) bf16 g_Qh[BNROWS*DDIM], g_Ql[BNROWS*DDIM];
__device__ __align__(256) bf16 g_Kh[BNROWS*DDIM], g_Kl[BNROWS*DDIM];
__device__ float g_V[BNROWS*DDIM];
__device__ float g_G[BNROWS*DDIM];
__device__ __align__(256) bf16 g_VGh[BNROWS*DDIM], g_VGl[BNROWS*DDIM];
__device__ __align__(256) bf16 g_Abh[(size_t)BDIM*HH*NSEQ*NSEQ];
__device__ __align__(256) bf16 g_Abl[(size_t)BDIM*HH*NSEQ*NSEQ];
__device__ __align__(256) bf16 g_Mh[BNROWS*DDIM], g_Ml[BNROWS*DDIM];
__device__ float g_Y[BNROWS*DDIM];
__device__ float g_Afb[(size_t)BDIM*HH*NSEQ*NSEQ];  // fallback if A not in output

// ---------------- small PTX helpers ----------------
__device__ __forceinline__ unsigned smem_u32(const void* p) {
    return (unsigned)__cvta_generic_to_shared(p);
}
__device__ __forceinline__ void cp16(unsigned dst, const void* src) {
    asm volatile("cp.async.ca.shared.global [%0], [%1], 16;\n" :: "r"(dst), "l"(src));
}
__device__ __forceinline__ void cp_commit() { asm volatile("cp.async.commit_group;\n" ::); }
template<int N> __device__ __forceinline__ void cp_wait() {
    asm volatile("cp.async.wait_group %0;\n" :: "n"(N));
}
__device__ __forceinline__ void ldm_x4(unsigned* d, unsigned addr) {
    asm volatile("ldmatrix.sync.aligned.m8n8.x4.shared.b16 {%0,%1,%2,%3}, [%4];"
                 : "=r"(d[0]), "=r"(d[1]), "=r"(d[2]), "=r"(d[3]) : "r"(addr));
}
__device__ __forceinline__ void ldm_x4t(unsigned* d, unsigned addr) {
    asm volatile("ldmatrix.sync.aligned.m8n8.x4.trans.shared.b16 {%0,%1,%2,%3}, [%4];"
                 : "=r"(d[0]), "=r"(d[1]), "=r"(d[2]), "=r"(d[3]) : "r"(addr));
}
__device__ __forceinline__ void mma_bf16(float* c, const unsigned* a, const unsigned* b) {
    asm volatile(
        "mma.sync.aligned.m16n8k16.row.col.f32.bf16.bf16.f32 "
        "{%0,%1,%2,%3},{%4,%5,%6,%7},{%8,%9},{%0,%1,%2,%3};"
        : "+f"(c[0]), "+f"(c[1]), "+f"(c[2]), "+f"(c[3])
        : "r"(a[0]), "r"(a[1]), "r"(a[2]), "r"(a[3]), "r"(b[0]), "r"(b[1]));
}
__device__ __forceinline__ void split_bf16(float v, bf16& h, bf16& l) {
    h = __float2bfloat16_rn(v);
    l = __float2bfloat16_rn(v - __bfloat162float(h));
}

// ---------------------------------------------------------------------------
// GEMM body: bf16x3 error-compensated, cp.async 2-stage pipeline.
// A: [M,K] row-major bf16 hi/lo. B: NN [K,N]; NT [N,K]. Outputs:
// optional fp32 Cf (+bias/act/alpha/resid) and/or bf16 hi/lo pair Ch/Cl.
// ---------------------------------------------------------------------------
template<int BM, int BN, int BK, int WM, int WN, bool BT, int THREADS>
__device__ __forceinline__ void gemm_body(
    int K,
    const bf16* __restrict__ Agh, const bf16* __restrict__ Agl, int lda,
    const bf16* __restrict__ Bgh, const bf16* __restrict__ Bgl, int ldb,
    float* Cf, bf16* Ch, bf16* Cl, int ldc,
    const float* bias, const float* resid, int ldr,
    float alpha, int act)
{
    constexpr int APITCH = BK + 8;
    constexpr int BROWS  = BT ? BN : BK;
    constexpr int BPITCH = BT ? (BK + 8) : (BN + 8);
    constexpr int ABYTES = BM * APITCH * 2;
    constexpr int BBYTES = BROWS * BPITCH * 2;
    constexpr int STAGE  = 2 * ABYTES + 2 * BBYTES;
    constexpr int MI = WM / 16, NJ = WN / 8;

    extern __shared__ char dsm[];

    const int tid  = threadIdx.x;
    const int lane = tid & 31;
    const int warp = tid >> 5;
    const int wm = warp % (BM/WM);
    const int wn = warp / (BM/WM);
    const int m0 = wm * WM, n0 = wn * WN;
    const int rowBase = blockIdx.y * BM;
    const int colBase = blockIdx.x * BN;
    const int lrow  = lane & 15;
    const int lkoff = (lane >> 4) << 3;

    float acc[MI][NJ][4];
#pragma unroll
    for (int i = 0; i < MI; i++)
#pragma unroll
        for (int j = 0; j < NJ; j++)
#pragma unroll
            for (int q = 0; q < 4; q++) acc[i][j][q] = 0.f;

    auto load_stage = [&](int s, int k0) {
        char* base = dsm + s * STAGE;
        bf16* Ash = (bf16*)(base);
        bf16* Asl = (bf16*)(base + ABYTES);
        bf16* Bsh = (bf16*)(base + 2*ABYTES);
        bf16* Bsl = (bf16*)(base + 2*ABYTES + BBYTES);
        constexpr int ACH = BM * BK / 8;
#pragma unroll
        for (int t = 0; t < ACH; t += THREADS) {
            int idx = t + tid;
            int r = idx / (BK/8);
            int c = (idx % (BK/8)) * 8;
            long so = (long)(rowBase + r) * lda + k0 + c;
            cp16(smem_u32(Ash + r*APITCH + c), Agh + so);
            cp16(smem_u32(Asl + r*APITCH + c), Agl + so);
        }
        if (BT) {
            constexpr int BCH = BN * BK / 8;
#pragma unroll
            for (int t = 0; t < BCH; t += THREADS) {
                int idx = t + tid;
                int r = idx / (BK/8);
                int c = (idx % (BK/8)) * 8;
                long so = (long)(colBase + r) * ldb + k0 + c;
                cp16(smem_u32(Bsh + r*BPITCH + c), Bgh + so);
                cp16(smem_u32(Bsl + r*BPITCH + c), Bgl + so);
            }
        } else {
            constexpr int BCH = BK * BN / 8;
#pragma unroll
            for (int t = 0; t < BCH; t += THREADS) {
                int idx = t + tid;
                int r = idx / (BN/8);
                int c = (idx % (BN/8)) * 8;
                long so = (long)(k0 + r) * ldb + colBase + c;
                cp16(smem_u32(Bsh + r*BPITCH + c), Bgh + so);
                cp16(smem_u32(Bsl + r*BPITCH + c), Bgl + so);
            }
        }
    };

    auto compute_stage = [&](int s) {
        char* base = dsm + s * STAGE;
        bf16* Ash = (bf16*)(base);
        bf16* Asl = (bf16*)(base + ABYTES);
        bf16* Bsh = (bf16*)(base + 2*ABYTES);
        bf16* Bsl = (bf16*)(base + 2*ABYTES + BBYTES);
#pragma unroll
        for (int kk = 0; kk < BK; kk += 16) {
            unsigned afh[MI][4], afl[MI][4];
            unsigned bfh[NJ][2], bfl[NJ][2];
#pragma unroll
            for (int mi = 0; mi < MI; mi++) {
                ldm_x4(afh[mi], smem_u32(Ash + (m0 + mi*16 + lrow)*APITCH + kk + lkoff));
                ldm_x4(afl[mi], smem_u32(Asl + (m0 + mi*16 + lrow)*APITCH + kk + lkoff));
            }
            if (BT) {
#pragma unroll
                for (int njp = 0; njp < NJ/2; njp++) {
                    unsigned r4[4];
                    ldm_x4(r4, smem_u32(Bsh + (n0 + njp*16 + lrow)*BPITCH + kk + lkoff));
                    bfh[2*njp][0]   = r4[0]; bfh[2*njp][1]   = r4[2];
                    bfh[2*njp+1][0] = r4[1]; bfh[2*njp+1][1] = r4[3];
                    ldm_x4(r4, smem_u32(Bsl + (n0 + njp*16 + lrow)*BPITCH + kk + lkoff));
                    bfl[2*njp][0]   = r4[0]; bfl[2*njp][1]   = r4[2];
                    bfl[2*njp+1][0] = r4[1]; bfl[2*njp+1][1] = r4[3];
                }
            } else {
#pragma unroll
                for (int nj = 0; nj < NJ; nj += 2) {
                    ldm_x4t(&bfh[nj][0], smem_u32(Bsh + (kk + lrow)*BPITCH + n0 + (nj + (lane>>4))*8));
                    ldm_x4t(&bfl[nj][0], smem_u32(Bsl + (kk + lrow)*BPITCH + n0 + (nj + (lane>>4))*8));
                }
            }
#pragma unroll
            for (int mi = 0; mi < MI; mi++)
#pragma unroll
                for (int nj = 0; nj < NJ; nj++) {
                    mma_bf16(acc[mi][nj], afh[mi], bfh[nj]);
                    mma_bf16(acc[mi][nj], afh[mi], bfl[nj]);
                    mma_bf16(acc[mi][nj], afl[mi], bfh[nj]);
                }
        }
    };

    const int KT = K / BK;
    load_stage(0, 0);
    cp_commit();
    for (int kt = 0; kt < KT; kt++) {
        if (kt + 1 < KT) {
            load_stage((kt + 1) & 1, (kt + 1) * BK);
            cp_commit();
            cp_wait<1>();
        } else {
            cp_wait<0>();
        }
        __syncthreads();
        compute_stage(kt & 1);
        __syncthreads();
    }

    // ---- epilogue ----
#pragma unroll
    for (int mi = 0; mi < MI; mi++) {
#pragma unroll
        for (int nj = 0; nj < NJ; nj++) {
            int c = colBase + n0 + nj*8 + 2*(lane & 3);
            float b0 = 0.f, b1 = 0.f;
            if (bias) { b0 = bias[c]; b1 = bias[c+1]; }
#pragma unroll
            for (int half = 0; half < 2; half++) {
                int r = rowBase + m0 + mi*16 + (lane >> 2) + half*8;
                float v0 = acc[mi][nj][half*2+0] * alpha + b0;
                float v1 = acc[mi][nj][half*2+1] * alpha + b1;
                if (act == 1) {
                    v0 = 1.f / (1.f + __expf(-v0));
                    v1 = 1.f / (1.f + __expf(-v1));
                }
                if (resid) {
                    v0 += resid[(long)r * ldr + c];
                    v1 += resid[(long)r * ldr + c + 1];
                }
                long off = (long)r * ldc + c;
                if (Cf) {
                    float2 o; o.x = v0; o.y = v1;
                    *(float2*)&Cf[off] = o;
                }
                if (Ch) {
                    bf16 h0, l0, h1, l1;
                    split_bf16(v0, h0, l0);
                    split_bf16(v1, h1, l1);
                    bf162 ph; ph.x = h0; ph.y = h1;
                    bf162 pl; pl.x = l0; pl.y = l1;
                    *(bf162*)&Ch[off] = ph;
                    *(bf162*)&Cl[off] = pl;
                }
            }
        }
    }
}

// multiplexed 4-projection kernel: z picks weight/bias/output/epilogue
struct Ptrs4 {
    const bf16* Bh[4]; const bf16* Bl[4];
    const float* bias[4];
    float* Cf[4]; bf16* Ch[4]; bf16* Cl[4];
    int act[4];
};

template<int BM, int BN, int BK, int WM, int WN>
__global__ __launch_bounds__((BM/WM)*(BN/WN)*32, 2)
void gemm4_kernel(int K, const bf16* __restrict__ Ah, const bf16* __restrict__ Al,
                  int lda, int ldb, int ldc, Ptrs4 p)
{
    int z = blockIdx.z;
    gemm_body<BM,BN,BK,WM,WN,false,(BM/WM)*(BN/WN)*32>(
        K, Ah, Al, lda, p.Bh[z], p.Bl[z], ldb,
        p.Cf[z], p.Ch[z], p.Cl[z], ldc,
        p.bias[z], nullptr, 0, 1.f, p.act[z]);
}

// batched (over b,h) GEMM kernel
template<int BM, int BN, int BK, int WM, int WN, bool BT>
__global__ __launch_bounds__((BM/WM)*(BN/WN)*32, 2)
void gemmb_kernel(int K,
                  const bf16* __restrict__ Ah, const bf16* __restrict__ Al, int lda, long sAb, long sAh,
                  const bf16* __restrict__ Bh, const bf16* __restrict__ Bl, int ldb, long sBb, long sBh,
                  float* Cf, bf16* Ch, bf16* Cl, int ldc, long sCb, long sCh,
                  const float* bias, const float* resid, int ldr,
                  float alpha, int act, int Hdiv)
{
    int z  = blockIdx.z;
    int bb = z / Hdiv;
    int hh = z - bb * Hdiv;
    const bf16* ah = Ah + bb*sAb + hh*sAh;
    const bf16* al = Al + bb*sAb + hh*sAh;
    const bf16* bh = Bh + bb*sBb + hh*sBh;
    const bf16* bl = Bl + bb*sBb + hh*sBh;
    long co = bb*sCb + hh*sCh;
    gemm_body<BM,BN,BK,WM,WN,BT,(BM/WM)*(BN/WN)*32>(
        K, ah, al, lda, bh, bl, ldb,
        Cf ? Cf + co : nullptr, Ch ? Ch + co : nullptr, Cl ? Cl + co : nullptr, ldc,
        bias, resid, ldr, alpha, act);
}

constexpr int stage_bytes_h(int BM, int BN, int BK, bool BT) {
    int AP = BK + 8;
    int BR = BT ? BN : BK;
    int BP = BT ? (BK + 8) : (BN + 8);
    return 2 * (BM * AP * 2) + 2 * (BR * BP * 2);
}

// ---------------- elementwise kernels ----------------
__global__ void split_kernel(const float* __restrict__ s, bf16* __restrict__ h, bf16* __restrict__ l)
{
    long i = ((long)blockIdx.x * blockDim.x + threadIdx.x) * 4;
    float4 v = *(const float4*)(s + i);
    bf16 h0,l0,h1,l1,h2,l2,h3,l3;
    split_bf16(v.x, h0, l0); split_bf16(v.y, h1, l1);
    split_bf16(v.z, h2, l2); split_bf16(v.w, h3, l3);
    bf162 p;
    p.x = h0; p.y = h1; *(bf162*)(h + i)     = p;
    p.x = h2; p.y = h3; *(bf162*)(h + i + 2) = p;
    p.x = l0; p.y = l1; *(bf162*)(l + i)     = p;
    p.x = l2; p.y = l3; *(bf162*)(l + i + 2) = p;
}

// VG = V * sigmoid(G) (G already post-sigmoid), split to bf16 pair
__global__ void vg_split_kernel(const float* __restrict__ V, const float* __restrict__ G,
                                bf16* __restrict__ h, bf16* __restrict__ l)
{
    long i = ((long)blockIdx.x * blockDim.x + threadIdx.x) * 4;
    float4 v = *(const float4*)(V + i);
    float4 g = *(const float4*)(G + i);
    v.x *= g.x; v.y *= g.y; v.z *= g.z; v.w *= g.w;
    bf16 h0,l0,h1,l1,h2,l2,h3,l3;
    split_bf16(v.x, h0, l0); split_bf16(v.y, h1, l1);
    split_bf16(v.z, h2, l2); split_bf16(v.w, h3, l3);
    bf162 p;
    p.x = h0; p.y = h1; *(bf162*)(h + i)     = p;
    p.x = h2; p.y = h3; *(bf162*)(h + i + 2) = p;
    p.x = l0; p.y = l1; *(bf162*)(l + i)     = p;
    p.x = l2; p.y = l3; *(bf162*)(l + i + 2) = p;
}

// In-place softmax over rows of length NSEQ, also emits bf16 hi/lo pair
__global__ void softmax_kernel(float* __restrict__ A, bf16* __restrict__ Oh, bf16* __restrict__ Ol)
{
    __shared__ float red[256];
    long row = blockIdx.x;
    float* p = A + row * (long)NSEQ;
    int tid = threadIdx.x;

    float4 a = ((const float4*)p)[tid];
    float4 b = ((const float4*)p)[tid + 256];

    float m = fmaxf(fmaxf(fmaxf(a.x, a.y), fmaxf(a.z, a.w)),
                    fmaxf(fmaxf(b.x, b.y), fmaxf(b.z, b.w)));
    red[tid] = m; __syncthreads();
    for (int o = 128; o > 0; o >>= 1) {
        if (tid < o) red[tid] = fmaxf(red[tid], red[tid + o]);
        __syncthreads();
    }
    m = red[0]; __syncthreads();

    a.x = expf(a.x - m); a.y = expf(a.y - m); a.z = expf(a.z - m); a.w = expf(a.w - m);
    b.x = expf(b.x - m); b.y = expf(b.y - m); b.z = expf(b.z - m); b.w = expf(b.w - m);
    float s = a.x + a.y + a.z + a.w + b.x + b.y + b.z + b.w;
    red[tid] = s; __syncthreads();
    for (int o = 128; o > 0; o >>= 1) {
        if (tid < o) red[tid] += red[tid + o];
        __syncthreads();
    }
    float inv = 1.f / red[0];

    a.x *= inv; a.y *= inv; a.z *= inv; a.w *= inv;
    b.x *= inv; b.y *= inv; b.z *= inv; b.w *= inv;
    ((float4*)p)[tid]       = a;
    ((float4*)p)[tid + 256] = b;

    long base = row * (long)NSEQ;
    float va[8] = {a.x, a.y, a.z, a.w, b.x, b.y, b.z, b.w};
    long offs[2] = {base + (long)tid*4, base + 1024 + (long)tid*4};
#pragma unroll
    for (int g2 = 0; g2 < 2; g2++) {
        bf16 h0,l0,h1,l1,h2,l2,h3,l3;
        split_bf16(va[g2*4+0], h0, l0); split_bf16(va[g2*4+1], h1, l1);
        split_bf16(va[g2*4+2], h2, l2); split_bf16(va[g2*4+3], h3, l3);
        bf162 ph;
        ph.x = h0; ph.y = h1; *(bf162*)(Oh + offs[g2])     = ph;
        ph.x = h2; ph.y = h3; *(bf162*)(Oh + offs[g2] + 2) = ph;
        ph.x = l0; ph.y = l1; *(bf162*)(Ol + offs[g2])     = ph;
        ph.x = l2; ph.y = l3; *(bf162*)(Ol + offs[g2] + 2) = ph;
    }
}

// LayerNorm over last dim (1024)
__global__ void ln_kernel(const float* __restrict__ Y,
                          const float* __restrict__ gamma,
                          const float* __restrict__ beta,
                          float* __restrict__ out)
{
    __shared__ float red[256];
    int row = blockIdx.x, tid = threadIdx.x;
    const float4* y4 = (const float4*)(Y + (long)row * DDIM);
    float4 v = y4[tid];

    red[tid] = v.x + v.y + v.z + v.w; __syncthreads();
    for (int o = 128; o > 0; o >>= 1) {
        if (tid < o) red[tid] += red[tid + o];
        __syncthreads();
    }
    float mean = red[0] * (1.f / DDIM);
    __syncthreads();

    float d0 = v.x - mean, d1 = v.y - mean, d2 = v.z - mean, d3 = v.w - mean;
    red[tid] = d0*d0 + d1*d1 + d2*d2 + d3*d3; __syncthreads();
    for (int o = 128; o > 0; o >>= 1) {
        if (tid < o) red[tid] += red[tid + o];
        __syncthreads();
    }
    float var = red[0] * (1.f / DDIM);
    float inv = rsqrtf(var + 1e-5f);

    float4 g  = ((const float4*)gamma)[tid];
    float4 bt = ((const float4*)beta)[tid];
    float4 o4;
    o4.x = g.x * (d0 * inv) + bt.x;
    o4.y = g.y * (d1 * inv) + bt.y;
    o4.z = g.z * (d2 * inv) + bt.z;
    o4.w = g.w * (d3 * inv) + bt.w;
    ((float4*)(out + (long)row * DDIM))[tid] = o4;
}

extern "C" void kernel_launch(void* const* d_in, const int* in_sizes, int n_in,
                              void* d_out, int out_size)
{
    const float* x     = (const float*)d_in[0];
    const float* Wq    = (const float*)d_in[1];
    const float* bq    = (const float*)d_in[2];
    const float* Wk    = (const float*)d_in[3];
    const float* bk    = (const float*)d_in[4];
    const float* Wv    = (const float*)d_in[5];
    const float* bv    = (const float*)d_in[6];
    const float* Wg    = (const float*)d_in[7];
    const float* bg    = (const float*)d_in[8];
    const float* Wp    = (const float*)d_in[9];
    const float* bp    = (const float*)d_in[10];
    const float* gamma = (const float*)d_in[11];
    const float* beta  = (const float*)d_in[12];
    float* outp = (float*)d_out;

    bf16 *xh, *xl, *wh, *wl, *Qh, *Ql, *Kh, *Kl, *VGh, *VGl, *Abh, *Abl, *Mh, *Ml;
    float *Vf, *Gf, *Y, *Afb;
    cudaGetSymbolAddress((void**)&xh,  g_xh);
    cudaGetSymbolAddress((void**)&xl,  g_xl);
    cudaGetSymbolAddress((void**)&wh,  g_wh);
    cudaGetSymbolAddress((void**)&wl,  g_wl);
    cudaGetSymbolAddress((void**)&Qh,  g_Qh);
    cudaGetSymbolAddress((void**)&Ql,  g_Ql);
    cudaGetSymbolAddress((void**)&Kh,  g_Kh);
    cudaGetSymbolAddress((void**)&Kl,  g_Kl);
    cudaGetSymbolAddress((void**)&Vf,  g_V);
    cudaGetSymbolAddress((void**)&Gf,  g_G);
    cudaGetSymbolAddress((void**)&VGh, g_VGh);
    cudaGetSymbolAddress((void**)&VGl, g_VGl);
    cudaGetSymbolAddress((void**)&Abh, g_Abh);
    cudaGetSymbolAddress((void**)&Abl, g_Abl);
    cudaGetSymbolAddress((void**)&Mh,  g_Mh);
    cudaGetSymbolAddress((void**)&Ml,  g_Ml);
    cudaGetSymbolAddress((void**)&Y,   g_Y);
    cudaGetSymbolAddress((void**)&Afb, g_Afb);

    float* A = ((long)out_size >= OUT1 + AELEMS) ? (outp + OUT1) : Afb;

    const long WSZ = (long)LDIM * DDIM;

    // 0) split x and the 5 weight matrices to bf16 hi/lo
    split_kernel<<<(BNROWS*(long)LDIM)/1024, 256>>>(x, xh, xl);
    split_kernel<<<WSZ/1024, 256>>>(Wq, wh + 0*WSZ, wl + 0*WSZ);
    split_kernel<<<WSZ/1024, 256>>>(Wk, wh + 1*WSZ, wl + 1*WSZ);
    split_kernel<<<WSZ/1024, 256>>>(Wv, wh + 2*WSZ, wl + 2*WSZ);
    split_kernel<<<WSZ/1024, 256>>>(Wg, wh + 3*WSZ, wl + 3*WSZ);
    split_kernel<<<WSZ/1024, 256>>>(Wp, wh + 4*WSZ, wl + 4*WSZ);

    constexpr int SM_PROJ = 2 * stage_bytes_h(128, 128, 32, false);   // 75776
    constexpr int SM_QKT  = 2 * stage_bytes_h(128, 128, 32, true);    // 81920
    constexpr int SM_AV   = 2 * stage_bytes_h(128, 64, 32, false);    // 59392

    cudaFuncSetAttribute(gemm4_kernel<128,128,32,64,32>,
                         cudaFuncAttributeMaxDynamicSharedMemorySize, SM_PROJ);
    cudaFuncSetAttribute(gemmb_kernel<128,128,32,64,32,true>,
                         cudaFuncAttributeMaxDynamicSharedMemorySize, SM_QKT);
    cudaFuncSetAttribute(gemmb_kernel<128,64,32,64,32,false>,
                         cudaFuncAttributeMaxDynamicSharedMemorySize, SM_AV);
    cudaFuncSetAttribute(gemmb_kernel<128,128,32,64,32,false>,
                         cudaFuncAttributeMaxDynamicSharedMemorySize, SM_PROJ);

    // 1) fused 4-way projections: z=0 Q(pair), z=1 K(pair), z=2 V(f32), z=3 sigmoid(G)(f32)
    {
        Ptrs4 p;
        p.Bh[0] = wh + 0*WSZ; p.Bl[0] = wl + 0*WSZ; p.bias[0] = bq;
        p.Cf[0] = nullptr; p.Ch[0] = Qh; p.Cl[0] = Ql; p.act[0] = 0;
        p.Bh[1] = wh + 1*WSZ; p.Bl[1] = wl + 1*WSZ; p.bias[1] = bk;
        p.Cf[1] = nullptr; p.Ch[1] = Kh; p.Cl[1] = Kl; p.act[1] = 0;
        p.Bh[2] = wh + 2*WSZ; p.Bl[2] = wl + 2*WSZ; p.bias[2] = bv;
        p.Cf[2] = Vf; p.Ch[2] = nullptr; p.Cl[2] = nullptr; p.act[2] = 0;
        p.Bh[3] = wh + 3*WSZ; p.Bl[3] = wl + 3*WSZ; p.bias[3] = bg;
        p.Cf[3] = Gf; p.Ch[3] = nullptr; p.Cl[3] = nullptr; p.act[3] = 1;
        dim3 grid(DDIM/128, BNROWS/128, 4);
        gemm4_kernel<128,128,32,64,32><<<grid, 256, SM_PROJ>>>(
            LDIM, xh, xl, LDIM, DDIM, DDIM, p);
    }

    // 2) VG = V * sigmoid(G) -> bf16 pair
    vg_split_kernel<<<(BNROWS*(long)DDIM)/1024, 256>>>(Vf, Gf, VGh, VGl);

    // 3) Scores: per (b,h): S = (1/8) * Qh @ Kh^T -> fp32 into A region
    {
        dim3 grid(NSEQ/128, NSEQ/128, BDIM*HH);
        gemmb_kernel<128,128,32,64,32,true><<<grid, 256, SM_QKT>>>(
            HDM,
            Qh, Ql, DDIM, (long)NSEQ*DDIM, HDM,
            Kh, Kl, DDIM, (long)NSEQ*DDIM, HDM,
            A, nullptr, nullptr, NSEQ, (long)HH*NSEQ*NSEQ, (long)NSEQ*NSEQ,
            nullptr, nullptr, 0, 0.125f, 0, HH);
    }

    // 4) softmax in place on A; also emit bf16 pair for AV
    softmax_kernel<<<BDIM*HH*NSEQ, 256>>>(A, Abh, Abl);

    // 5) M = A @ VG per (b,h) -> bf16 pair
    {
        dim3 grid(1, NSEQ/128, BDIM*HH);
        gemmb_kernel<128,64,32,64,32,false><<<grid, 128, SM_AV>>>(
            NSEQ,
            Abh, Abl, NSEQ, (long)HH*NSEQ*NSEQ, (long)NSEQ*NSEQ,
            VGh, VGl, DDIM, (long)NSEQ*DDIM, HDM,
            nullptr, Mh, Ml, DDIM, (long)NSEQ*DDIM, HDM,
            nullptr, nullptr, 0, 1.f, 0, HH);
    }

    // 6) Y = x + M @ Wp + bp
    {
        dim3 grid(DDIM/128, BNROWS/128, 1);
        gemmb_kernel<128,128,32,64,32,false><<<grid, 256, SM_PROJ>>>(
            DDIM,
            Mh, Ml, DDIM, 0, 0,
            wh + 4*WSZ, wl + 4*WSZ, DDIM, 0, 0,
            Y, nullptr, nullptr, DDIM, 0, 0,
            bp, x, DDIM, 1.f, 0, 1);
    }

    // 7) LayerNorm -> out
    ln_kernel<<<BNROWS, 256>>>(Y, gamma, beta, outp);
}

// round 5
// speedup vs baseline: 3.2351x; 1.1784x over previous
#include <cuda_runtime.h>
#include <cuda_bf16.h>
#include <math.h>

#define BDIM 2
#define NSEQ 2048
#define LDIM 1024
#define DDIM 1024
#define HH   16
#define HDM  64
#define BNROWS (BDIM*NSEQ)   // 4096
#define SM_SCALE 0.125f

static const long OUT1   = (long)BDIM * NSEQ * DDIM;        // 4,194,304
static const long AELEMS = (long)BDIM * HH * NSEQ * NSEQ;   // 134,217,728

typedef __nv_bfloat16 bf16;
typedef __nv_bfloat162 bf162;

// ---------------- device scratch (no cudaMalloc anywhere) ----------------
__device__ __align__(256) bf16 g_xh[BNROWS*LDIM], g_xl[BNROWS*LDIM];
__device__ __align__(256) bf16 g_wh[5][LDIM*DDIM], g_wl[5][LDIM*DDIM];
__device__ __align__(256) bf16 g_Qh[BNROWS*DDIM], g_Ql[BNROWS*DDIM];
__device__ __align__(256) bf16 g_Kh[BNROWS*DDIM], g_Kl[BNROWS*DDIM];
__device__ float g_V[BNROWS*DDIM];
__device__ float g_G[BNROWS*DDIM];
__device__ __align__(256) bf16 g_VGh[BNROWS*DDIM];
__device__ __align__(256) bf16 g_Mh[BNROWS*DDIM];
__device__ float g_Y[BNROWS*DDIM];
__device__ float g_Afb[(size_t)BDIM*HH*NSEQ*NSEQ];  // fallback if A not in output

// ---------------- PTX helpers ----------------
__device__ __forceinline__ unsigned smem_u32(const void* p) {
    return (unsigned)__cvta_generic_to_shared(p);
}
__device__ __forceinline__ void cp16(unsigned dst, const void* src) {
    asm volatile("cp.async.ca.shared.global [%0], [%1], 16;\n" :: "r"(dst), "l"(src));
}
__device__ __forceinline__ void cp_commit() { asm volatile("cp.async.commit_group;\n" ::); }
template<int N> __device__ __forceinline__ void cp_wait() {
    asm volatile("cp.async.wait_group %0;\n" :: "n"(N));
}
__device__ __forceinline__ void ldm_x4(unsigned* d, unsigned addr) {
    asm volatile("ldmatrix.sync.aligned.m8n8.x4.shared.b16 {%0,%1,%2,%3}, [%4];"
                 : "=r"(d[0]), "=r"(d[1]), "=r"(d[2]), "=r"(d[3]) : "r"(addr));
}
__device__ __forceinline__ void ldm_x4t(unsigned* d, unsigned addr) {
    asm volatile("ldmatrix.sync.aligned.m8n8.x4.trans.shared.b16 {%0,%1,%2,%3}, [%4];"
                 : "=r"(d[0]), "=r"(d[1]), "=r"(d[2]), "=r"(d[3]) : "r"(addr));
}
__device__ __forceinline__ void mma_bf16(float* c, const unsigned* a, const unsigned* b) {
    asm volatile(
        "mma.sync.aligned.m16n8k16.row.col.f32.bf16.bf16.f32 "
        "{%0,%1,%2,%3},{%4,%5,%6,%7},{%8,%9},{%0,%1,%2,%3};"
        : "+f"(c[0]), "+f"(c[1]), "+f"(c[2]), "+f"(c[3])
        : "r"(a[0]), "r"(a[1]), "r"(a[2]), "r"(a[3]), "r"(b[0]), "r"(b[1]));
}
__device__ __forceinline__ void split_bf16(float v, bf16& h, bf16& l) {
    h = __float2bfloat16_rn(v);
    l = __float2bfloat16_rn(v - __bfloat162float(h));
}
__device__ __forceinline__ unsigned pack2(float a, float b) {
    bf162 t; t.x = __float2bfloat16_rn(a); t.y = __float2bfloat16_rn(b);
    return *(unsigned*)&t;
}

// ---------------------------------------------------------------------------
// GEMM body: bf16 tensor-core GEMM, cp.async 2-stage pipeline.
// full=true -> bf16x3 error-compensated (hi/lo). full=false -> hi-only.
// ---------------------------------------------------------------------------
template<int BM, int BN, int BK, int WM, int WN, int THREADS>
__device__ __forceinline__ void gemm_body(
    int K, bool full,
    const bf16* __restrict__ Agh, const bf16* __restrict__ Agl, int lda,
    const bf16* __restrict__ Bgh, const bf16* __restrict__ Bgl, int ldb,
    float* Cf, bf16* Ch, bf16* Cl, int ldc,
    const float* bias, const float* resid, int ldr,
    float alpha, int act)
{
    constexpr int APITCH = BK + 8;
    constexpr int BPITCH = BN + 8;
    constexpr int ABYTES = BM * APITCH * 2;
    constexpr int BBYTES = BK * BPITCH * 2;
    constexpr int STAGE  = 2 * ABYTES + 2 * BBYTES;
    constexpr int MI = WM / 16, NJ = WN / 8;

    extern __shared__ char dsm[];

    const int tid  = threadIdx.x;
    const int lane = tid & 31;
    const int warp = tid >> 5;
    const int wm = warp % (BM/WM);
    const int wn = warp / (BM/WM);
    const int m0 = wm * WM, n0 = wn * WN;
    const int rowBase = blockIdx.y * BM;
    const int colBase = blockIdx.x * BN;
    const int lrow  = lane & 15;
    const int lkoff = (lane >> 4) << 3;

    float acc[MI][NJ][4];
#pragma unroll
    for (int i = 0; i < MI; i++)
#pragma unroll
        for (int j = 0; j < NJ; j++)
#pragma unroll
            for (int q = 0; q < 4; q++) acc[i][j][q] = 0.f;

    auto load_stage = [&](int s, int k0) {
        char* base = dsm + s * STAGE;
        bf16* Ash = (bf16*)(base);
        bf16* Asl = (bf16*)(base + ABYTES);
        bf16* Bsh = (bf16*)(base + 2*ABYTES);
        bf16* Bsl = (bf16*)(base + 2*ABYTES + BBYTES);
        constexpr int ACH = BM * BK / 8;
#pragma unroll
        for (int t = 0; t < ACH; t += THREADS) {
            int idx = t + tid;
            int r = idx / (BK/8);
            int c = (idx % (BK/8)) * 8;
            long so = (long)(rowBase + r) * lda + k0 + c;
            cp16(smem_u32(Ash + r*APITCH + c), Agh + so);
            if (full) cp16(smem_u32(Asl + r*APITCH + c), Agl + so);
        }
        constexpr int BCH = BK * BN / 8;
#pragma unroll
        for (int t = 0; t < BCH; t += THREADS) {
            int idx = t + tid;
            int r = idx / (BN/8);
            int c = (idx % (BN/8)) * 8;
            long so = (long)(k0 + r) * ldb + colBase + c;
            cp16(smem_u32(Bsh + r*BPITCH + c), Bgh + so);
            if (full) cp16(smem_u32(Bsl + r*BPITCH + c), Bgl + so);
        }
    };

    auto compute_stage = [&](int s) {
        char* base = dsm + s * STAGE;
        bf16* Ash = (bf16*)(base);
        bf16* Asl = (bf16*)(base + ABYTES);
        bf16* Bsh = (bf16*)(base + 2*ABYTES);
        bf16* Bsl = (bf16*)(base + 2*ABYTES + BBYTES);
#pragma unroll
        for (int kk = 0; kk < BK; kk += 16) {
            unsigned afh[MI][4], afl[MI][4];
            unsigned bfh[NJ][2], bfl[NJ][2];
#pragma unroll
            for (int mi = 0; mi < MI; mi++) {
                ldm_x4(afh[mi], smem_u32(Ash + (m0 + mi*16 + lrow)*APITCH + kk + lkoff));
                if (full) ldm_x4(afl[mi], smem_u32(Asl + (m0 + mi*16 + lrow)*APITCH + kk + lkoff));
            }
#pragma unroll
            for (int nj = 0; nj < NJ; nj += 2) {
                ldm_x4t(&bfh[nj][0], smem_u32(Bsh + (kk + lrow)*BPITCH + n0 + (nj + (lane>>4))*8));
                if (full) ldm_x4t(&bfl[nj][0], smem_u32(Bsl + (kk + lrow)*BPITCH + n0 + (nj + (lane>>4))*8));
            }
#pragma unroll
            for (int mi = 0; mi < MI; mi++)
#pragma unroll
                for (int nj = 0; nj < NJ; nj++) {
                    mma_bf16(acc[mi][nj], afh[mi], bfh[nj]);
                    if (full) {
                        mma_bf16(acc[mi][nj], afh[mi], bfl[nj]);
                        mma_bf16(acc[mi][nj], afl[mi], bfh[nj]);
                    }
                }
        }
    };

    const int KT = K / BK;
    load_stage(0, 0);
    cp_commit();
    for (int kt = 0; kt < KT; kt++) {
        if (kt + 1 < KT) {
            load_stage((kt + 1) & 1, (kt + 1) * BK);
            cp_commit();
            cp_wait<1>();
        } else {
            cp_wait<0>();
        }
        __syncthreads();
        compute_stage(kt & 1);
        __syncthreads();
    }

    // ---- epilogue ----
#pragma unroll
    for (int mi = 0; mi < MI; mi++) {
#pragma unroll
        for (int nj = 0; nj < NJ; nj++) {
            int c = colBase + n0 + nj*8 + 2*(lane & 3);
            float b0 = 0.f, b1 = 0.f;
            if (bias) { b0 = bias[c]; b1 = bias[c+1]; }
#pragma unroll
            for (int half = 0; half < 2; half++) {
                int r = rowBase + m0 + mi*16 + (lane >> 2) + half*8;
                float v0 = acc[mi][nj][half*2+0] * alpha + b0;
                float v1 = acc[mi][nj][half*2+1] * alpha + b1;
                if (act == 1) {
                    v0 = 1.f / (1.f + __expf(-v0));
                    v1 = 1.f / (1.f + __expf(-v1));
                }
                if (resid) {
                    v0 += resid[(long)r * ldr + c];
                    v1 += resid[(long)r * ldr + c + 1];
                }
                long off = (long)r * ldc + c;
                if (Cf) {
                    float2 o; o.x = v0; o.y = v1;
                    *(float2*)&Cf[off] = o;
                }
                if (Ch) {
                    bf16 h0, l0, h1, l1;
                    split_bf16(v0, h0, l0);
                    split_bf16(v1, h1, l1);
                    bf162 ph; ph.x = h0; ph.y = h1;
                    bf162 pl; pl.x = l0; pl.y = l1;
                    *(bf162*)&Ch[off] = ph;
                    *(bf162*)&Cl[off] = pl;
                }
            }
        }
    }
}

// multiplexed 4-projection kernel
struct Ptrs4 {
    const bf16* Bh[4]; const bf16* Bl[4];
    const float* bias[4];
    float* Cf[4]; bf16* Ch[4]; bf16* Cl[4];
    int act[4]; int full[4];
};

template<int BM, int BN, int BK, int WM, int WN>
__global__ __launch_bounds__((BM/WM)*(BN/WN)*32, 2)
void gemm4_kernel(int K, const bf16* __restrict__ Ah, const bf16* __restrict__ Al,
                  int lda, int ldb, int ldc, Ptrs4 p)
{
    int z = blockIdx.z;
    gemm_body<BM,BN,BK,WM,WN,(BM/WM)*(BN/WN)*32>(
        K, p.full[z] != 0, Ah, Al, lda, p.Bh[z], p.Bl[z], ldb,
        p.Cf[z], p.Ch[z], p.Cl[z], ldc,
        p.bias[z], nullptr, 0, 1.f, p.act[z]);
}

// single GEMM (out projection)
template<int BM, int BN, int BK, int WM, int WN>
__global__ __launch_bounds__((BM/WM)*(BN/WN)*32, 2)
void gemm1_kernel(int K, int full,
                  const bf16* __restrict__ Ah, const bf16* __restrict__ Al, int lda,
                  const bf16* __restrict__ Bh, const bf16* __restrict__ Bl, int ldb,
                  float* Cf, int ldc,
                  const float* bias, const float* resid, int ldr)
{
    gemm_body<BM,BN,BK,WM,WN,(BM/WM)*(BN/WN)*32>(
        K, full != 0, Ah, Al, lda, Bh, Bl, ldb,
        Cf, nullptr, nullptr, ldc, bias, resid, ldr, 1.f, 0);
}

constexpr int stage_bytes_h(int BM, int BN, int BK) {
    return 2 * (BM * (BK + 8) * 2) + 2 * (BK * (BN + 8) * 2);
}

// ---------------------------------------------------------------------------
// Fused attention: per CTA = 128 query rows x one (b,h).
// Pass 1: S = scale*Q@K^T streamed per 16-key group -> online row max/sum.
// Pass 2: recompute S bit-identically, P = exp(s-m)/l, write A (fp32, once),
//         and accumulate M += P @ VG via C-frag -> A-frag repack (hi-only PV).
// smem (110592B): [0,36864) QhQl (pass1) / pass2 stage0 K+V overlays;
//                 pass1 K double-buffer at 36864 & 73728.
// ---------------------------------------------------------------------------
#define QP 72  // smem pitch (elems) for 64-wide tiles

__global__ __launch_bounds__(256, 2)
void attn_kernel(const bf16* __restrict__ Qhg, const bf16* __restrict__ Qlg,
                 const bf16* __restrict__ Khg, const bf16* __restrict__ Klg,
                 const bf16* __restrict__ Vhg,
                 float* __restrict__ Ag, bf16* __restrict__ Mhg)
{
    extern __shared__ char sm[];
    const int tid = threadIdx.x, lane = tid & 31, warp = tid >> 5;
    const int bh = blockIdx.y, bb = bh >> 4, hh = bh & 15;
    const int q0 = blockIdx.x * 128;
    const long qrow = (long)bb * NSEQ + q0;
    const bf16* Qh = Qhg + qrow * DDIM + hh * HDM;
    const bf16* Ql = Qlg + qrow * DDIM + hh * HDM;
    const bf16* Kh = Khg + (long)bb * NSEQ * DDIM + hh * HDM;
    const bf16* Kl = Klg + (long)bb * NSEQ * DDIM + hh * HDM;
    const bf16* Vh = Vhg + (long)bb * NSEQ * DDIM + hh * HDM;
    float* Arow = Ag + ((long)(bb * HH + hh) * NSEQ + q0) * NSEQ;

    bf16* Qs = (bf16*)sm;
    const int lrow = lane & 15, lk = (lane >> 4) * 8;

    auto loadQ = [&]() {
        for (int t = tid; t < 2048; t += 256) {
            int hl = t >> 10, rem = t & 1023, r = rem >> 3, c = (rem & 7) * 8;
            const bf16* s = (hl ? Ql : Qh) + (long)r * DDIM + c;
            cp16(smem_u32(Qs + hl * 128 * QP + r * QP + c), s);
        }
    };
    auto loadKtile = [&](char* dst, int key0) {
        for (int t = tid; t < 2048; t += 256) {
            int hl = t >> 10, rem = t & 1023, r = rem >> 3, c = (rem & 7) * 8;
            const bf16* s = (hl ? Kl : Kh) + (long)(key0 + r) * DDIM + c;
            cp16(smem_u32((bf16*)dst + hl * 128 * QP + r * QP + c), s);
        }
    };
    auto loadVtile = [&](char* dst, int key0) {
        for (int t = tid; t < 1024; t += 256) {
            int r = t >> 3, c = (t & 7) * 8;
            cp16(smem_u32((bf16*)dst + r * QP + c), Vh + (long)(key0 + r) * DDIM + c);
        }
    };

    // ---- prologue: Q + first K tile ----
    loadQ();
    loadKtile(sm + 36864, 0);
    cp_commit(); cp_wait<0>(); __syncthreads();

    // preload Q fragments (constant through both passes)
    unsigned aqh[4][4], aql[4][4];
#pragma unroll
    for (int kk = 0; kk < 4; kk++) {
        ldm_x4(aqh[kk], smem_u32(Qs + (warp*16 + lrow)*QP + kk*16 + lk));
        ldm_x4(aql[kk], smem_u32(Qs + 128*QP + (warp*16 + lrow)*QP + kk*16 + lk));
    }

    // deterministic S for one 16-key group (identical in both passes)
    auto computeS = [&](const char* kb, int kg, float (&c)[2][4]) {
        const bf16* Ksh = (const bf16*)kb;
        const bf16* Ksl = Ksh + 128 * QP;
#pragma unroll
        for (int kk = 0; kk < 4; kk++) {
            unsigned rh[4], rl[4];
            ldm_x4(rh, smem_u32(Ksh + (kg*16 + lrow)*QP + kk*16 + lk));
            ldm_x4(rl, smem_u32(Ksl + (kg*16 + lrow)*QP + kk*16 + lk));
            unsigned b0h[2] = {rh[0], rh[2]}, b1h[2] = {rh[1], rh[3]};
            unsigned b0l[2] = {rl[0], rl[2]}, b1l[2] = {rl[1], rl[3]};
            mma_bf16(c[0], aqh[kk], b0h);
            mma_bf16(c[0], aqh[kk], b0l);
            mma_bf16(c[0], aql[kk], b0h);
            mma_bf16(c[1], aqh[kk], b1h);
            mma_bf16(c[1], aqh[kk], b1l);
            mma_bf16(c[1], aql[kk], b1h);
        }
    };

    // ---- pass 1: online max & sum ----
    float mr[2] = {-1e30f, -1e30f}, lr[2] = {0.f, 0.f};
    for (int kt = 0; kt < 16; kt++) {
        char* cur = sm + 36864 + (kt & 1) * 36864;
        if (kt < 15) {
            char* pre = sm + 36864 + ((kt + 1) & 1) * 36864;
            loadKtile(pre, (kt + 1) * 128);
            cp_commit();
        }
#pragma unroll 1
        for (int kg = 0; kg < 8; kg++) {
            float c[2][4] = {};
            computeS(cur, kg, c);
#pragma unroll
            for (int rr = 0; rr < 2; rr++) {
                float s0 = c[0][rr*2]   * SM_SCALE;
                float s1 = c[0][rr*2+1] * SM_SCALE;
                float s2 = c[1][rr*2]   * SM_SCALE;
                float s3 = c[1][rr*2+1] * SM_SCALE;
                float tm = fmaxf(fmaxf(s0, s1), fmaxf(s2, s3));
                tm = fmaxf(tm, __shfl_xor_sync(0xffffffff, tm, 1));
                tm = fmaxf(tm, __shfl_xor_sync(0xffffffff, tm, 2));
                float mn = fmaxf(mr[rr], tm);
                float corr = __expf(mr[rr] - mn);
                float es = __expf(s0 - mn) + __expf(s1 - mn) + __expf(s2 - mn) + __expf(s3 - mn);
                es += __shfl_xor_sync(0xffffffff, es, 1);
                es += __shfl_xor_sync(0xffffffff, es, 2);
                lr[rr] = lr[rr] * corr + es;
                mr[rr] = mn;
            }
        }
        if (kt < 15) { cp_wait<0>(); __syncthreads(); }
    }

    float invl[2] = {1.f / lr[0], 1.f / lr[1]};

    // ---- pass 2: recompute S, write A, accumulate M = P @ V ----
    float Macc[8][4] = {};
    __syncthreads();   // everyone done with pass-1 buffers
    loadKtile(sm, 0);               // stage0: K at [0,36864), V at [36864,55296)
    loadVtile(sm + 36864, 0);
    cp_commit(); cp_wait<0>(); __syncthreads();

    for (int kt = 0; kt < 16; kt++) {
        char* stg = sm + (kt & 1) * 55296;
        if (kt < 15) {
            char* pre = sm + ((kt + 1) & 1) * 55296;
            loadKtile(pre, (kt + 1) * 128);
            loadVtile(pre + 36864, (kt + 1) * 128);
            cp_commit();
        }
        const bf16* Vs = (const bf16*)(stg + 36864);
#pragma unroll 1
        for (int kg = 0; kg < 8; kg++) {
            float c[2][4] = {};
            computeS(stg, kg, c);
            float p[2][4];
#pragma unroll
            for (int nj = 0; nj < 2; nj++) {
                p[nj][0] = __expf(c[nj][0] * SM_SCALE - mr[0]) * invl[0];
                p[nj][1] = __expf(c[nj][1] * SM_SCALE - mr[0]) * invl[0];
                p[nj][2] = __expf(c[nj][2] * SM_SCALE - mr[1]) * invl[1];
                p[nj][3] = __expf(c[nj][3] * SM_SCALE - mr[1]) * invl[1];
            }
            // write normalized A (fp32), 32B-sector-aligned float2 stores
            long colb = (long)kt * 128 + kg * 16 + 2 * (lane & 3);
            long r0 = warp * 16 + (lane >> 2);
            float2 w;
            w.x = p[0][0]; w.y = p[0][1]; *(float2*)&Arow[r0*NSEQ + colb]           = w;
            w.x = p[1][0]; w.y = p[1][1]; *(float2*)&Arow[r0*NSEQ + colb + 8]       = w;
            w.x = p[0][2]; w.y = p[0][3]; *(float2*)&Arow[(r0+8)*NSEQ + colb]       = w;
            w.x = p[1][2]; w.y = p[1][3]; *(float2*)&Arow[(r0+8)*NSEQ + colb + 8]   = w;
            // repack P (C-frag) as mma A-frag (hi-only)
            unsigned pa[4];
            pa[0] = pack2(p[0][0], p[0][1]);
            pa[1] = pack2(p[0][2], p[0][3]);
            pa[2] = pack2(p[1][0], p[1][1]);
            pa[3] = pack2(p[1][2], p[1][3]);
            // P @ V for this 16-key group
#pragma unroll
            for (int njp = 0; njp < 4; njp++) {
                unsigned bv[4];
                ldm_x4t(bv, smem_u32(Vs + (kg*16 + lrow)*QP + (njp*2 + (lane>>4))*8));
                unsigned b0[2] = {bv[0], bv[1]}, b1[2] = {bv[2], bv[3]};
                mma_bf16(Macc[njp*2],     pa, b0);
                mma_bf16(Macc[njp*2 + 1], pa, b1);
            }
        }
        if (kt < 15) { cp_wait<0>(); __syncthreads(); }
    }

    // ---- epilogue: M -> bf16 (hi) ----
    long mrow0 = qrow + warp * 16 + (lane >> 2);
#pragma unroll
    for (int njv = 0; njv < 8; njv++) {
        int col = hh * HDM + njv * 8 + 2 * (lane & 3);
        bf162 ph;
        ph.x = __float2bfloat16_rn(Macc[njv][0]);
        ph.y = __float2bfloat16_rn(Macc[njv][1]);
        *(bf162*)&Mhg[mrow0 * DDIM + col] = ph;
        ph.x = __float2bfloat16_rn(Macc[njv][2]);
        ph.y = __float2bfloat16_rn(Macc[njv][3]);
        *(bf162*)&Mhg[(mrow0 + 8) * DDIM + col] = ph;
    }
}

// ---------------- elementwise kernels ----------------
__global__ void split_kernel(const float* __restrict__ s, bf16* __restrict__ h, bf16* __restrict__ l)
{
    long i = ((long)blockIdx.x * blockDim.x + threadIdx.x) * 4;
    float4 v = *(const float4*)(s + i);
    bf16 h0,l0,h1,l1,h2,l2,h3,l3;
    split_bf16(v.x, h0, l0); split_bf16(v.y, h1, l1);
    split_bf16(v.z, h2, l2); split_bf16(v.w, h3, l3);
    bf162 p;
    p.x = h0; p.y = h1; *(bf162*)(h + i)     = p;
    p.x = h2; p.y = h3; *(bf162*)(h + i + 2) = p;
    p.x = l0; p.y = l1; *(bf162*)(l + i)     = p;
    p.x = l2; p.y = l3; *(bf162*)(l + i + 2) = p;
}

// VG = V * sigmoid(G) -> bf16 (hi only; PV path is damped)
__global__ void vg_kernel(const float* __restrict__ V, const float* __restrict__ G,
                          bf16* __restrict__ h)
{
    long i = ((long)blockIdx.x * blockDim.x + threadIdx.x) * 4;
    float4 v = *(const float4*)(V + i);
    float4 g = *(const float4*)(G + i);
    bf162 p;
    p.x = __float2bfloat16_rn(v.x * g.x);
    p.y = __float2bfloat16_rn(v.y * g.y);
    *(bf162*)(h + i) = p;
    p.x = __float2bfloat16_rn(v.z * g.z);
    p.y = __float2bfloat16_rn(v.w * g.w);
    *(bf162*)(h + i + 2) = p;
}

// LayerNorm over last dim (1024)
__global__ void ln_kernel(const float* __restrict__ Y,
                          const float* __restrict__ gamma,
                          const float* __restrict__ beta,
                          float* __restrict__ out)
{
    __shared__ float red[256];
    int row = blockIdx.x, tid = threadIdx.x;
    const float4* y4 = (const float4*)(Y + (long)row * DDIM);
    float4 v = y4[tid];

    red[tid] = v.x + v.y + v.z + v.w; __syncthreads();
    for (int o = 128; o > 0; o >>= 1) {
        if (tid < o) red[tid] += red[tid + o];
        __syncthreads();
    }
    float mean = red[0] * (1.f / DDIM);
    __syncthreads();

    float d0 = v.x - mean, d1 = v.y - mean, d2 = v.z - mean, d3 = v.w - mean;
    red[tid] = d0*d0 + d1*d1 + d2*d2 + d3*d3; __syncthreads();
    for (int o = 128; o > 0; o >>= 1) {
        if (tid < o) red[tid] += red[tid + o];
        __syncthreads();
    }
    float var = red[0] * (1.f / DDIM);
    float inv = rsqrtf(var + 1e-5f);

    float4 g  = ((const float4*)gamma)[tid];
    float4 bt = ((const float4*)beta)[tid];
    float4 o4;
    o4.x = g.x * (d0 * inv) + bt.x;
    o4.y = g.y * (d1 * inv) + bt.y;
    o4.z = g.z * (d2 * inv) + bt.z;
    o4.w = g.w * (d3 * inv) + bt.w;
    ((float4*)(out + (long)row * DDIM))[tid] = o4;
}

extern "C" void kernel_launch(void* const* d_in, const int* in_sizes, int n_in,
                              void* d_out, int out_size)
{
    const float* x     = (const float*)d_in[0];
    const float* Wq    = (const float*)d_in[1];
    const float* bq    = (const float*)d_in[2];
    const float* Wk    = (const float*)d_in[3];
    const float* bk    = (const float*)d_in[4];
    const float* Wv    = (const float*)d_in[5];
    const float* bv    = (const float*)d_in[6];
    const float* Wg    = (const float*)d_in[7];
    const float* bg    = (const float*)d_in[8];
    const float* Wp    = (const float*)d_in[9];
    const float* bp    = (const float*)d_in[10];
    const float* gamma = (const float*)d_in[11];
    const float* beta  = (const float*)d_in[12];
    float* outp = (float*)d_out;

    bf16 *xh, *xl, *wh, *wl, *Qh, *Ql, *Kh, *Kl, *VGh, *Mh;
    float *Vf, *Gf, *Y, *Afb;
    cudaGetSymbolAddress((void**)&xh,  g_xh);
    cudaGetSymbolAddress((void**)&xl,  g_xl);
    cudaGetSymbolAddress((void**)&wh,  g_wh);
    cudaGetSymbolAddress((void**)&wl,  g_wl);
    cudaGetSymbolAddress((void**)&Qh,  g_Qh);
    cudaGetSymbolAddress((void**)&Ql,  g_Ql);
    cudaGetSymbolAddress((void**)&Kh,  g_Kh);
    cudaGetSymbolAddress((void**)&Kl,  g_Kl);
    cudaGetSymbolAddress((void**)&Vf,  g_V);
    cudaGetSymbolAddress((void**)&Gf,  g_G);
    cudaGetSymbolAddress((void**)&VGh, g_VGh);
    cudaGetSymbolAddress((void**)&Mh,  g_Mh);
    cudaGetSymbolAddress((void**)&Y,   g_Y);
    cudaGetSymbolAddress((void**)&Afb, g_Afb);

    float* A = ((long)out_size >= OUT1 + AELEMS) ? (outp + OUT1) : Afb;

    const long WSZ = (long)LDIM * DDIM;

    // 0) splits
    split_kernel<<<(BNROWS*(long)LDIM)/1024, 256>>>(x, xh, xl);
    split_kernel<<<WSZ/1024, 256>>>(Wq, wh + 0*WSZ, wl + 0*WSZ);
    split_kernel<<<WSZ/1024, 256>>>(Wk, wh + 1*WSZ, wl + 1*WSZ);
    split_kernel<<<WSZ/1024, 256>>>(Wv, wh + 2*WSZ, wl + 2*WSZ);
    split_kernel<<<WSZ/1024, 256>>>(Wg, wh + 3*WSZ, wl + 3*WSZ);
    split_kernel<<<WSZ/1024, 256>>>(Wp, wh + 4*WSZ, wl + 4*WSZ);

    constexpr int SM_PROJ = 2 * stage_bytes_h(128, 128, 32);
    constexpr int SM_ATTN = 110592;

    cudaFuncSetAttribute(gemm4_kernel<128,128,32,64,32>,
                         cudaFuncAttributeMaxDynamicSharedMemorySize, SM_PROJ);
    cudaFuncSetAttribute(gemm1_kernel<128,128,32,64,32>,
                         cudaFuncAttributeMaxDynamicSharedMemorySize, SM_PROJ);
    cudaFuncSetAttribute(attn_kernel,
                         cudaFuncAttributeMaxDynamicSharedMemorySize, SM_ATTN);

    // 1) fused projections: z0 Q(pair,x3), z1 K(pair,x3), z2 V(f32,x1), z3 sigmoid G(f32,x1)
    {
        Ptrs4 p;
        p.Bh[0] = wh + 0*WSZ; p.Bl[0] = wl + 0*WSZ; p.bias[0] = bq;
        p.Cf[0] = nullptr; p.Ch[0] = Qh; p.Cl[0] = Ql; p.act[0] = 0; p.full[0] = 1;
        p.Bh[1] = wh + 1*WSZ; p.Bl[1] = wl + 1*WSZ; p.bias[1] = bk;
        p.Cf[1] = nullptr; p.Ch[1] = Kh; p.Cl[1] = Kl; p.act[1] = 0; p.full[1] = 1;
        p.Bh[2] = wh + 2*WSZ; p.Bl[2] = wl + 2*WSZ; p.bias[2] = bv;
        p.Cf[2] = Vf; p.Ch[2] = nullptr; p.Cl[2] = nullptr; p.act[2] = 0; p.full[2] = 0;
        p.Bh[3] = wh + 3*WSZ; p.Bl[3] = wl + 3*WSZ; p.bias[3] = bg;
        p.Cf[3] = Gf; p.Ch[3] = nullptr; p.Cl[3] = nullptr; p.act[3] = 1; p.full[3] = 0;
        dim3 grid(DDIM/128, BNROWS/128, 4);
        gemm4_kernel<128,128,32,64,32><<<grid, 256, SM_PROJ>>>(
            LDIM, xh, xl, LDIM, DDIM, DDIM, p);
    }

    // 2) VG = V * sigmoid(G) -> bf16 hi
    vg_kernel<<<(BNROWS*(long)DDIM)/1024, 256>>>(Vf, Gf, VGh);

    // 3-5) fused attention: A (fp32, exact softmax) + M = A @ VG (bf16 hi)
    {
        dim3 grid(NSEQ/128, BDIM*HH);
        attn_kernel<<<grid, 256, SM_ATTN>>>(Qh, Ql, Kh, Kl, VGh, A, Mh);
    }

    // 6) Y = x + M @ Wp + bp (hi-only; damped by residual)
    {
        dim3 grid(DDIM/128, BNROWS/128, 1);
        gemm1_kernel<128,128,32,64,32><<<grid, 256, SM_PROJ>>>(
            DDIM, 0,
            Mh, Mh, DDIM,
            wh + 4*WSZ, wl + 4*WSZ, DDIM,
            Y, DDIM, bp, x, DDIM);
    }

    // 7) LayerNorm -> out
    ln_kernel<<<BNROWS, 256>>>(Y, gamma, beta, outp);
}